// round 15
// baseline (speedup 1.0000x reference)
#include <cuda_runtime.h>
#include <cstdint>
#include <cstddef>

// Problem constants (fixed by the dataset)
#define NN   8192      // NP == NQ
#define CAP  128       // ELL capacity per row
#define TW   768       // concatenated linear output width (3 x 256)

// -------- scratch (no allocations allowed) --------
__device__ float g_scratch[2 * NN * TW + 2 * NN * 256];
__device__ int   g_ell[4 * NN * CAP + 4 * NN];

#define WSTRIDE 12   // smem row stride in 32-bit words (8 data + 4 pad): conflict-free

struct GemmSmem {
    uint32_t sA[2][2][128 * WSTRIDE];
    uint32_t sB[2][2][64 * WSTRIDE];
};

// ============================================================================
// bf16 2-way split helpers + m16n8k16 MMA
// ============================================================================
__device__ __forceinline__ void bfsplit2(float x0, float x1, uint32_t& h, uint32_t& l) {
    // h = {bf16(x1) : bf16(x0)}, l = packed residuals
    asm("cvt.rn.bf16x2.f32 %0, %1, %2;" : "=r"(h) : "f"(x1), "f"(x0));
    float r0 = x0 - __uint_as_float(h << 16);
    float r1 = x1 - __uint_as_float(h & 0xffff0000u);
    asm("cvt.rn.bf16x2.f32 %0, %1, %2;" : "=r"(l) : "f"(r1), "f"(r0));
}

__device__ __forceinline__ void mma_bf16(float* d, const uint32_t* a, const uint32_t* b) {
    asm volatile(
        "mma.sync.aligned.m16n8k16.row.col.f32.bf16.bf16.f32 "
        "{%0,%1,%2,%3}, {%4,%5,%6,%7}, {%8,%9}, {%0,%1,%2,%3};\n"
        : "+f"(d[0]), "+f"(d[1]), "+f"(d[2]), "+f"(d[3])
        : "r"(a[0]), "r"(a[1]), "r"(a[2]), "r"(a[3]), "r"(b[0]), "r"(b[1]));
}

// ============================================================================
// GEMM body: Y[:,cb*64:(cb+1)*64] block (bx) = X @ Wsel^T + bias (bf16x3)
// Block tile 128(M) x 64(N), BK=16, 8 warps (4m x 2n), warp tile 32x32.
// ============================================================================
template <int K>
__device__ __forceinline__ void gemm_body(
    const float* __restrict__ X,
    const float* __restrict__ W0, const float* __restrict__ W1, const float* __restrict__ W2,
    const float* __restrict__ B0, const float* __restrict__ B1, const float* __restrict__ B2,
    float* __restrict__ Y, int bx, int cb, GemmSmem& sm)
{
    const int m0 = bx * 128;
    const int wsel = cb >> 2;
    const float* W  = (wsel == 0) ? W0 : (wsel == 1) ? W1 : W2;
    const float* Bv = (wsel == 0) ? B0 : (wsel == 1) ? B1 : B2;
    const int nW = (cb & 3) * 64;               // row offset inside W [256,K]

    const int tid  = threadIdx.x;
    const int lane = tid & 31, warp = tid >> 5;
    const int wm = warp >> 1, wn = warp & 1;    // 4 x 2 warps
    const int g  = lane >> 2, tig = lane & 3;

    // global load assignments (BK = 16 fp32)
    const int arow = tid >> 1, alc = (tid & 1) * 8;   // A: 128 rows x 16k, 2x float4/thread
    const int brow = tid >> 2, blc = (tid & 3) * 4;   // B: 64 rows x 16k, 1x float4/thread
    const float* Ap = X + (size_t)(m0 + arow) * K + alc;
    const float* Bp = W + (size_t)(nW + brow) * K + blc;

    float acc[2][4][4];
#pragma unroll
    for (int mt = 0; mt < 2; mt++)
#pragma unroll
        for (int nt = 0; nt < 4; nt++)
#pragma unroll
            for (int i = 0; i < 4; i++) acc[mt][nt][i] = 0.f;

    constexpr int NT = K / 16;

    float4 av0, av1, bv;

    auto fillA = [&](int st, const float4& a0, const float4& a1) {
        uint4 h4, l4;
        bfsplit2(a0.x, a0.y, h4.x, l4.x);
        bfsplit2(a0.z, a0.w, h4.y, l4.y);
        bfsplit2(a1.x, a1.y, h4.z, l4.z);
        bfsplit2(a1.z, a1.w, h4.w, l4.w);
        *(uint4*)&sm.sA[st][0][arow * WSTRIDE + alc / 2] = h4;
        *(uint4*)&sm.sA[st][1][arow * WSTRIDE + alc / 2] = l4;
    };
    auto fillB = [&](int st, const float4& b0) {
        uint2 h2, l2;
        bfsplit2(b0.x, b0.y, h2.x, l2.x);
        bfsplit2(b0.z, b0.w, h2.y, l2.y);
        *(uint2*)&sm.sB[st][0][brow * WSTRIDE + blc / 2] = h2;
        *(uint2*)&sm.sB[st][1][brow * WSTRIDE + blc / 2] = l2;
    };

    // ---- preload tile 0 ----
    av0 = *(const float4*)(Ap);
    av1 = *(const float4*)(Ap + 4);
    bv  = *(const float4*)(Bp);
    fillA(0, av0, av1);
    fillB(0, bv);
    __syncthreads();

#pragma unroll 1
    for (int t = 0; t < NT; t++) {
        const int cur = t & 1;
        if (t + 1 < NT) {
            av0 = *(const float4*)(Ap + (t + 1) * 16);
            av1 = *(const float4*)(Ap + (t + 1) * 16 + 4);
            bv  = *(const float4*)(Bp + (t + 1) * 16);
        }

        uint32_t ah[2][4], al[2][4], bh[4][2], bl[4][2];
        const uint32_t* AsH = sm.sA[cur][0]; const uint32_t* AsL = sm.sA[cur][1];
        const uint32_t* BsH = sm.sB[cur][0]; const uint32_t* BsL = sm.sB[cur][1];
#pragma unroll
        for (int mt = 0; mt < 2; mt++) {
            const int r0 = (wm * 32 + mt * 16 + g) * WSTRIDE;
            const int r8 = r0 + 8 * WSTRIDE;
            ah[mt][0] = AsH[r0 + tig];
            ah[mt][1] = AsH[r8 + tig];
            ah[mt][2] = AsH[r0 + tig + 4];
            ah[mt][3] = AsH[r8 + tig + 4];
            al[mt][0] = AsL[r0 + tig];
            al[mt][1] = AsL[r8 + tig];
            al[mt][2] = AsL[r0 + tig + 4];
            al[mt][3] = AsL[r8 + tig + 4];
        }
#pragma unroll
        for (int nt = 0; nt < 4; nt++) {
            const int r = (wn * 32 + nt * 8 + g) * WSTRIDE;
            bh[nt][0] = BsH[r + tig];
            bh[nt][1] = BsH[r + tig + 4];
            bl[nt][0] = BsL[r + tig];
            bl[nt][1] = BsL[r + tig + 4];
        }

#pragma unroll
        for (int mt = 0; mt < 2; mt++)
#pragma unroll
            for (int nt = 0; nt < 4; nt++) {
                mma_bf16(acc[mt][nt], ah[mt], bh[nt]);   // hi*hi
                mma_bf16(acc[mt][nt], ah[mt], bl[nt]);   // hi*lo
                mma_bf16(acc[mt][nt], al[mt], bh[nt]);   // lo*hi
            }

        if (t + 1 < NT) {
            const int nxt = cur ^ 1;
            fillA(nxt, av0, av1);
            fillB(nxt, bv);
            __syncthreads();
        }
    }

    // ---- epilogue: bias + store ----
#pragma unroll
    for (int mt = 0; mt < 2; mt++) {
        const int r0 = m0 + wm * 32 + mt * 16 + g;
#pragma unroll
        for (int nt = 0; nt < 4; nt++) {
            const int cl = wn * 32 + nt * 8 + 2 * tig;   // 0..63 within block col tile
            const float b0 = Bv[nW + cl], b1 = Bv[nW + cl + 1];
            const int c = cb * 64 + cl;
            float2 v0 = {acc[mt][nt][0] + b0, acc[mt][nt][1] + b1};
            float2 v1 = {acc[mt][nt][2] + b0, acc[mt][nt][3] + b1};
            *(float2*)&Y[(size_t)r0 * TW + c]       = v0;
            *(float2*)&Y[(size_t)(r0 + 8) * TW + c] = v1;
        }
    }
}

// ============================================================================
// Build body: one block scans 8 adjacency rows -> ELL (warp/row, unroll x2,
// both float4 loads hoisted before ballots for MLP=2; order unchanged).
// ============================================================================
__device__ __forceinline__ void build_body(
    const float* __restrict__ A, int xblk, int mat, int* __restrict__ ell)
{
    const int row  = xblk * 8 + (threadIdx.x >> 5);
    const int lane = threadIdx.x & 31;

    const float4* ar = (const float4*)(A + (size_t)row * NN);
    int* idx  = ell + (size_t)mat * NN * CAP + (size_t)row * CAP;
    int* cntp = ell + (size_t)4 * NN * CAP + mat * NN + row;

    int cnt = 0;
#pragma unroll 1
    for (int base = 0; base < NN / 4; base += 64) {
        float4 v0 = ar[base + lane];
        float4 v1 = ar[base + 32 + lane];
#pragma unroll
        for (int h = 0; h < 2; h++) {
            const float4 v = (h == 0) ? v0 : v1;
            const int col0 = (base + h * 32 + lane) * 4;
            float e[4] = {v.x, v.y, v.z, v.w};
#pragma unroll
            for (int c = 0; c < 4; c++) {
                unsigned m = __ballot_sync(0xffffffffu, e[c] != 0.0f);
                if (e[c] != 0.0f) {
                    int pos = cnt + __popc(m & ((1u << lane) - 1u));
                    if (pos < CAP) idx[pos] = col0 + c;
                }
                cnt += __popc(m);
            }
        }
    }
    if (lane == 0) *cntp = (cnt < CAP) ? cnt : CAP;
}

// ============================================================================
// Fused layer-1 kernel: 1536 gemm blocks + 4096 build blocks, interleaved 3:8
// so both types are co-resident (GEMM = tensor-bound, build = DRAM-bound).
// grid = 5632 = 512 * 11;  bid%11<3 -> gemm, else -> build.
// ============================================================================
__global__ __launch_bounds__(256, 2) void fused_l1(
    const float* __restrict__ hp, const float* __restrict__ hq,
    const float* __restrict__ A0, const float* __restrict__ A1,
    const float* __restrict__ A2, const float* __restrict__ A3,
    const float* __restrict__ wp0, const float* __restrict__ wp1, const float* __restrict__ wp2,
    const float* __restrict__ bp0, const float* __restrict__ bp1, const float* __restrict__ bp2,
    const float* __restrict__ wq0, const float* __restrict__ wq1, const float* __restrict__ wq2,
    const float* __restrict__ bq0, const float* __restrict__ bq1, const float* __restrict__ bq2,
    float* __restrict__ Tp, float* __restrict__ Tq, int* __restrict__ ell)
{
    __shared__ GemmSmem sm;
    const int bid = blockIdx.x;
    const int r = bid % 11, q = bid / 11;
    if (r < 3) {
        const int gidx = q * 3 + r;              // 0..1535
        if (gidx < 768)
            gemm_body<512>(hp, wp0, wp1, wp2, bp0, bp1, bp2, Tp, gidx & 63, gidx >> 6, sm);
        else {
            const int gi = gidx - 768;
            gemm_body<512>(hq, wq0, wq1, wq2, bq0, bq1, bq2, Tq, gi & 63, gi >> 6, sm);
        }
    } else {
        const int bidx = q * 8 + (r - 3);        // 0..4095
        const int mat  = bidx >> 10;
        const float* A = (mat == 0) ? A0 : (mat == 1) ? A1 : (mat == 2) ? A2 : A3;
        build_body(A, bidx & 1023, mat, ell);
    }
}

// ============================================================================
// Merged layer-2 gemm: blockIdx.y in [0,24); y<12 -> P-side, else Q-side.
// Per-block work identical to the split version.
// ============================================================================
__global__ __launch_bounds__(256, 2) void gemm3_k256_2(
    const float* __restrict__ Xp, const float* __restrict__ Xq,
    const float* __restrict__ wp0, const float* __restrict__ wp1, const float* __restrict__ wp2,
    const float* __restrict__ bp0, const float* __restrict__ bp1, const float* __restrict__ bp2,
    const float* __restrict__ wq0, const float* __restrict__ wq1, const float* __restrict__ wq2,
    const float* __restrict__ bq0, const float* __restrict__ bq1, const float* __restrict__ bq2,
    float* __restrict__ Yp, float* __restrict__ Yq)
{
    __shared__ GemmSmem sm;
    const int cb = blockIdx.y;
    if (cb < 12)
        gemm_body<256>(Xp, wp0, wp1, wp2, bp0, bp1, bp2, Yp, blockIdx.x, cb, sm);
    else
        gemm_body<256>(Xq, wq0, wq1, wq2, bq0, bq1, bq2, Yq, blockIdx.x, cb - 12, sm);
}

// ============================================================================
// Combine body (unchanged per-block work): 4 rows/block, 64 thr/row, float4.
// ============================================================================
__device__ __forceinline__ void combine_body(
    const float* __restrict__ Tself, const float* __restrict__ Tother,
    const int* __restrict__ idx1, const int* __restrict__ cnt1,
    const int* __restrict__ idx2, const int* __restrict__ cnt2,
    float* __restrict__ outp, int do_norm, int bx)
{
    __shared__ int   sidx[4][2 * CAP];
    __shared__ float sred[8];
    const int tid = threadIdx.x;
    const int grp = tid >> 6, gt = tid & 63;
    const int row = bx * 4 + grp;

    {
        const int4* p1 = (const int4*)(idx1 + (size_t)row * CAP);
        const int4* p2 = (const int4*)(idx2 + (size_t)row * CAP);
        int4 v = (gt < 32) ? p1[gt] : p2[gt - 32];
        ((int4*)sidx[grp])[gt] = v;
    }
    const int c1 = cnt1[row];
    const int c2 = cnt2[row];
    __syncthreads();

    const int* si = sidx[grp];
    float4 s0 = *(const float4*)&Tself[(size_t)row * TW + 4 * gt];
    float4 s1 = {0.f, 0.f, 0.f, 0.f}, s2 = {0.f, 0.f, 0.f, 0.f}, s3 = {0.f, 0.f, 0.f, 0.f};

    const float* b1 = Tother + 256 + 4 * gt;
    const float* b2 = Tother + 512 + 4 * gt;

    int j = 0;
    for (; j + 4 <= c1; j += 4) {
        float4 v0 = *(const float4*)(b1 + (size_t)si[j + 0] * TW);
        float4 v1 = *(const float4*)(b1 + (size_t)si[j + 1] * TW);
        float4 v2 = *(const float4*)(b1 + (size_t)si[j + 2] * TW);
        float4 v3 = *(const float4*)(b1 + (size_t)si[j + 3] * TW);
        s0.x += v0.x; s0.y += v0.y; s0.z += v0.z; s0.w += v0.w;
        s1.x += v1.x; s1.y += v1.y; s1.z += v1.z; s1.w += v1.w;
        s2.x += v2.x; s2.y += v2.y; s2.z += v2.z; s2.w += v2.w;
        s3.x += v3.x; s3.y += v3.y; s3.z += v3.z; s3.w += v3.w;
    }
    for (; j < c1; j++) {
        float4 v = *(const float4*)(b1 + (size_t)si[j] * TW);
        s0.x += v.x; s0.y += v.y; s0.z += v.z; s0.w += v.w;
    }
    for (j = 0; j + 4 <= c2; j += 4) {
        float4 v0 = *(const float4*)(b2 + (size_t)si[CAP + j + 0] * TW);
        float4 v1 = *(const float4*)(b2 + (size_t)si[CAP + j + 1] * TW);
        float4 v2 = *(const float4*)(b2 + (size_t)si[CAP + j + 2] * TW);
        float4 v3 = *(const float4*)(b2 + (size_t)si[CAP + j + 3] * TW);
        s0.x += v0.x; s0.y += v0.y; s0.z += v0.z; s0.w += v0.w;
        s1.x += v1.x; s1.y += v1.y; s1.z += v1.z; s1.w += v1.w;
        s2.x += v2.x; s2.y += v2.y; s2.z += v2.z; s2.w += v2.w;
        s3.x += v3.x; s3.y += v3.y; s3.z += v3.z; s3.w += v3.w;
    }
    for (; j < c2; j++) {
        float4 v = *(const float4*)(b2 + (size_t)si[CAP + j] * TW);
        s0.x += v.x; s0.y += v.y; s0.z += v.z; s0.w += v.w;
    }

    float4 a;
    a.x = (s0.x + s1.x) + (s2.x + s3.x);
    a.y = (s0.y + s1.y) + (s2.y + s3.y);
    a.z = (s0.z + s1.z) + (s2.z + s3.z);
    a.w = (s0.w + s1.w) + (s2.w + s3.w);
    a.x = (a.x > 0.f) ? a.x : 0.1f * a.x;
    a.y = (a.y > 0.f) ? a.y : 0.1f * a.y;
    a.z = (a.z > 0.f) ? a.z : 0.1f * a.z;
    a.w = (a.w > 0.f) ? a.w : 0.1f * a.w;

    if (do_norm) {
        float sq = a.x * a.x + a.y * a.y + a.z * a.z + a.w * a.w;
#pragma unroll
        for (int s = 16; s > 0; s >>= 1)
            sq += __shfl_xor_sync(0xffffffffu, sq, s);
        if ((gt & 31) == 0) sred[grp * 2 + (gt >> 5)] = sq;
        __syncthreads();
        const float tot = sred[grp * 2] + sred[grp * 2 + 1];
        const float inv = 1.0f / (sqrtf(tot) + 1e-9f);
        a.x *= inv; a.y *= inv; a.z *= inv; a.w *= inv;
    }
    *(float4*)&outp[(size_t)row * 256 + 4 * gt] = a;
}

// Merged combine: blocks [0, 2048) = P side, [2048, 4096) = Q side.
__global__ __launch_bounds__(256) void combine2(
    const float* __restrict__ Tp, const float* __restrict__ Tq,
    const int* __restrict__ i0, const int* __restrict__ c0,
    const int* __restrict__ i3, const int* __restrict__ c3,
    const int* __restrict__ i1, const int* __restrict__ c1,
    const int* __restrict__ i2, const int* __restrict__ c2,
    float* __restrict__ outP, float* __restrict__ outQ, int do_norm)
{
    const int nb = NN / 4;                      // 2048
    if (blockIdx.x < nb) {
        // hp-side: self=Tp, other=Tq, lists (a_cons, a_rev_prod)
        combine_body(Tp, Tq, i0, c0, i3, c3, outP, do_norm, blockIdx.x);
    } else {
        // hq-side: self=Tq, other=Tp, lists (a_prod, a_rev_cons)
        combine_body(Tq, Tp, i1, c1, i2, c2, outQ, do_norm, blockIdx.x - nb);
    }
}

// ============================================================================
// Host orchestration (graph-capturable: kernel launches only)
// ============================================================================
extern "C" void kernel_launch(void* const* d_in, const int* in_sizes, int n_in,
                              void* d_out, int out_size)
{
    const float* hp      = (const float*)d_in[0];
    const float* hq      = (const float*)d_in[1];
    const float* a_cons  = (const float*)d_in[2];
    const float* a_prod  = (const float*)d_in[3];
    const float* a_rcons = (const float*)d_in[4];
    const float* a_rprod = (const float*)d_in[5];
    const float* w[12];
    const float* b[12];
    for (int i = 0; i < 12; i++) {
        w[i] = (const float*)d_in[6 + 2 * i];
        b[i] = (const float*)d_in[7 + 2 * i];
    }
    float* out = (float*)d_out;

    float* scratch = nullptr;
    int*   ell     = nullptr;
    cudaGetSymbolAddress((void**)&scratch, g_scratch);
    cudaGetSymbolAddress((void**)&ell, g_ell);

    float* Tp  = scratch;
    float* Tq  = scratch + (size_t)NN * TW;
    float* hp1 = scratch + (size_t)2 * NN * TW;
    float* hq1 = hp1 + (size_t)NN * 256;

    int* idx[4];
    int* cnt[4];
    for (int m = 0; m < 4; m++) {
        idx[m] = ell + (size_t)m * NN * CAP;
        cnt[m] = ell + (size_t)4 * NN * CAP + (size_t)m * NN;
    }

    // ---- fused: ELL build + layer-1 gemms (independent work, co-resident) ----
    // mats: 0 = a_cons [P,Q], 1 = a_prod [Q,P], 2 = a_rev_cons [Q,P], 3 = a_rev_prod [P,Q]
    fused_l1<<<5632, 256>>>(hp, hq, a_cons, a_prod, a_rcons, a_rprod,
                            w[0], w[4], w[5], b[0], b[4], b[5],
                            w[1], w[2], w[3], b[1], b[2], b[3],
                            Tp, Tq, ell);

    // ---- layer 1 combines (merged P+Q) ----
    combine2<<<NN / 2, 256>>>(Tp, Tq,
                              idx[0], cnt[0], idx[3], cnt[3],
                              idx[1], cnt[1], idx[2], cnt[2],
                              hp1, hq1, 0);

    // ---- layer 2 gemms (merged P+Q) ----
    gemm3_k256_2<<<dim3(64, 24), 256>>>(hp1, hq1,
                                        w[6], w[10], w[11], b[6], b[10], b[11],
                                        w[7], w[8],  w[9],  b[7], b[8],  b[9],
                                        Tp, Tq);

    // ---- layer 2 combines (merged P+Q, normalized) ----
    combine2<<<NN / 2, 256>>>(Tp, Tq,
                              idx[0], cnt[0], idx[3], cnt[3],
                              idx[1], cnt[1], idx[2], cnt[2],
                              out, out + (size_t)NN * 256, 1);
}